// round 7
// baseline (speedup 1.0000x reference)
#include <cuda_runtime.h>

#define N_NODES 100000
#define N_EDGES 1000000
#define D 64

typedef unsigned long long u64t;

// Scratch: device globals (no allocs allowed). float4 => 16B aligned.
__device__ float4 g_y4[(size_t)N_NODES * (D / 4)];    // message MLP output
__device__ float4 g_agg4[(size_t)N_NODES * (D / 4)];  // scatter-sum accumulator
__device__ int    g_ei_is64;                          // 1 if edge_index is int64

// ---- packed f32x2 helpers (Blackwell dual-FP32 pipe) ----
__device__ __forceinline__ void fma2(u64t& d, u64t a, u64t b) {
    asm("fma.rn.f32x2 %0, %1, %2, %0;" : "+l"(d) : "l"(a), "l"(b));
}
__device__ __forceinline__ void upk2(u64t p, float& a, float& b) {
    asm("mov.b64 {%0, %1}, %2;" : "=f"(a), "=f"(b) : "l"(p));
}

// Weight 16B-chunk permutation: swaps adjacent chunks in odd 8-chunk groups.
// Makes the 8-lane b-fragment reads (32B stride) hit distinct banks.
__device__ __forceinline__ int wperm(int j) { return j ^ ((j >> 3) & 1); }

// ---------------------------------------------------------------------------
// K0: zero agg + detect edge_index dtype (int64 LE => odd 32-bit words == 0)
// ---------------------------------------------------------------------------
__global__ void k_zero_agg(const int* __restrict__ ei32) {
    int idx = blockIdx.x * blockDim.x + threadIdx.x;
    const int n4 = N_NODES * (D / 4);
    if (idx < n4) g_agg4[idx] = make_float4(0.f, 0.f, 0.f, 0.f);
    if (blockIdx.x == 0 && threadIdx.x == 0) {
        int is64 = 1;
        for (int i = 0; i < 64; i++)
            if (ei32[2 * i + 1] != 0) { is64 = 0; break; }
        g_ei_is64 = is64;
    }
}

// ---------------------------------------------------------------------------
// MLP building blocks. CTA = 512 threads; tile = 256 rows x 64 cols (linear).
// Warp grid: 8 row-warps x 2 col-warps; thread tile 8 rows x 4 cols.
// Accumulators: acc[i][c] = u64, halves = partial sums over even/odd k.
// ---------------------------------------------------------------------------

// Stage 256x64 gmem slab into linear smem tile (zero-padded past N_NODES).
__device__ __forceinline__ void stage_tile(float* xs, const float4* src4,
                                           int n0, int tid) {
#pragma unroll
    for (int it = 0; it < 8; it++) {
        int i = tid + it * 512;
        float4 v = make_float4(0.f, 0.f, 0.f, 0.f);
        if (n0 + (i >> 4) < N_NODES) v = src4[i];
        ((float4*)xs)[i] = v;
    }
}

// Stage Krows x 64 row-major weights into k-pair-interleaved, chunk-permuted
// layout: float index = kp*128 + wperm(c>>1)*4 + (c&1)*2 + (k&1).
__device__ __forceinline__ void stage_w(float* ws, const float* __restrict__ w,
                                        int Krows, int tid) {
    for (int idx = tid; idx < Krows * 64; idx += 512) {
        int k = idx >> 6, c = idx & 63;
        int f = (k >> 1) * 128 + wperm(c >> 1) * 4 + (c & 1) * 2 + (k & 1);
        ws[f] = w[idx];
    }
}

__device__ __forceinline__ void zero_acc(u64t acc[8][4]) {
#pragma unroll
    for (int i = 0; i < 8; i++)
#pragma unroll
        for (int p = 0; p < 4; p++) acc[i][p] = 0ull;
}

// acc += tile[r0..r0+7][k] * W[k][c0..c0+3]  for k in [0,64)
__device__ __forceinline__ void sweep(u64t acc[8][4], const float* xs,
                                      const float* ws, int r0, int pc0, int pc1) {
#pragma unroll 2
    for (int kb = 0; kb < 16; kb++) {          // 4 k per block
        ulonglong2 a[8];
#pragma unroll
        for (int i = 0; i < 8; i++)
            a[i] = *(const ulonglong2*)(xs + (r0 + i) * 64 + kb * 4);
        const float* wrow = ws + kb * 256;      // 2 kp-rows of 128 floats
#pragma unroll
        for (int half = 0; half < 2; half++) {  // k-pair within block
            ulonglong2 bA = *(const ulonglong2*)(wrow + half * 128 + pc0);
            ulonglong2 bB = *(const ulonglong2*)(wrow + half * 128 + pc1);
#pragma unroll
            for (int i = 0; i < 8; i++) {
                u64t a2 = half ? a[i].y : a[i].x;   // (k,k+1) f32 pair, no movs
                fma2(acc[i][0], a2, bA.x);
                fma2(acc[i][1], a2, bA.y);
                fma2(acc[i][2], a2, bB.x);
                fma2(acc[i][3], a2, bB.y);
            }
        }
    }
}

// relu(lo+hi+bias) -> tile rows r0..r0+7, cols c0..c0+3 (float4 stores).
__device__ __forceinline__ void finalize_relu_tile(float* xs, u64t acc[8][4],
                                                   const float* __restrict__ bias,
                                                   int r0, int c0) {
    float b0 = bias[c0], b1 = bias[c0 + 1], b2 = bias[c0 + 2], b3 = bias[c0 + 3];
#pragma unroll
    for (int i = 0; i < 8; i++) {
        float e0, o0, e1, o1, e2, o2, e3, o3;
        upk2(acc[i][0], e0, o0); upk2(acc[i][1], e1, o1);
        upk2(acc[i][2], e2, o2); upk2(acc[i][3], e3, o3);
        float4 v;
        v.x = fmaxf(e0 + o0 + b0, 0.f);
        v.y = fmaxf(e1 + o1 + b1, 0.f);
        v.z = fmaxf(e2 + o2 + b2, 0.f);
        v.w = fmaxf(e3 + o3 + b3, 0.f);
        *(float4*)(xs + (r0 + i) * 64 + c0) = v;
    }
}

// (lo+hi+bias) -> gmem rows (guarded), float4 per row.
__device__ __forceinline__ void finalize_store(float* dst, u64t acc[8][4],
                                               const float* __restrict__ bias,
                                               int n0, int r0, int c0) {
    float b0 = bias[c0], b1 = bias[c0 + 1], b2 = bias[c0 + 2], b3 = bias[c0 + 3];
#pragma unroll
    for (int i = 0; i < 8; i++) {
        int n = n0 + r0 + i;
        if (n < N_NODES) {
            float e0, o0, e1, o1, e2, o2, e3, o3;
            upk2(acc[i][0], e0, o0); upk2(acc[i][1], e1, o1);
            upk2(acc[i][2], e2, o2); upk2(acc[i][3], e3, o3);
            float4 v = make_float4(e0 + o0 + b0, e1 + o1 + b1,
                                   e2 + o2 + b2, e3 + o3 + b3);
            *(float4*)(dst + (size_t)n * D + c0) = v;
        }
    }
}

// ---------------------------------------------------------------------------
// K1: node message MLP  y = relu(x @ W1 + b1) @ W2 + b2      [N,64]
// ---------------------------------------------------------------------------
#define K1_SMEM_FLOATS (256 * 64 + 4096 + 4096)

__global__ __launch_bounds__(512, 1) void k_msg_mlp(
    const float* __restrict__ x,
    const float* __restrict__ w1, const float* __restrict__ b1,
    const float* __restrict__ w2, const float* __restrict__ b2)
{
    extern __shared__ float sm[];
    float* xs  = sm;               // 256*64 tile (x, then h)
    float* w1t = xs + 256 * 64;    // 4096 (pair-interleaved)
    float* w2t = w1t + 4096;       // 4096

    const int tid = threadIdx.x;
    const int n0  = blockIdx.x * 256;
    const int lane = tid & 31, warp = tid >> 5;
    const int r0 = (warp & 7) * 32 + (lane >> 3) * 8;
    const int c0 = (warp >> 3) * 32 + (lane & 7) * 4;
    const int j0 = c0 >> 1;
    const int pc0 = wperm(j0) * 4, pc1 = wperm(j0 + 1) * 4;

    stage_w(w1t, w1, 64, tid);
    stage_w(w2t, w2, 64, tid);
    stage_tile(xs, (const float4*)(x + (size_t)n0 * D), n0, tid);
    __syncthreads();

    u64t acc[8][4];
    zero_acc(acc);
    sweep(acc, xs, w1t, r0, pc0, pc1);
    __syncthreads();                       // all x-tile reads done
    finalize_relu_tile(xs, acc, b1, r0, c0);
    __syncthreads();

    zero_acc(acc);
    sweep(acc, xs, w2t, r0, pc0, pc1);
    finalize_store((float*)g_y4, acc, b2, n0, r0, c0);
}

// ---------------------------------------------------------------------------
// K2: scatter  agg[col] += y[row]  via red.global.add.v4.f32
// ---------------------------------------------------------------------------
__global__ __launch_bounds__(256) void k_scatter(const void* __restrict__ ei_raw)
{
    long long tid = (long long)blockIdx.x * blockDim.x + threadIdx.x;
    if (tid >= (long long)N_EDGES * 16) return;
    int e = (int)(tid >> 4);
    int c = (int)(tid & 15);

    int row, col;
    if (g_ei_is64) {
        const long long* ei = (const long long*)ei_raw;
        row = (int)ei[e];
        col = (int)ei[N_EDGES + e];
    } else {
        const int* ei = (const int*)ei_raw;
        row = ei[e];
        col = ei[N_EDGES + e];
    }
    if ((unsigned)row >= N_NODES || (unsigned)col >= N_NODES) return;

    const float4 v = g_y4[(size_t)row * (D / 4) + c];
    float4* p = g_agg4 + (size_t)col * (D / 4) + c;
    asm volatile("red.global.add.v4.f32 [%0], {%1,%2,%3,%4};"
                 :: "l"(p), "f"(v.x), "f"(v.y), "f"(v.z), "f"(v.w)
                 : "memory");
}

// ---------------------------------------------------------------------------
// K3: output MLP  out = relu([x,agg] @ W1 + b1) @ W2 + b2     [N,64]
// Two-pass layer 1: x tile vs W1[0:64], agg tile vs W1[64:128].
// ---------------------------------------------------------------------------
#define K3_SMEM_FLOATS (256 * 64 + 8192 + 4096)

__global__ __launch_bounds__(512, 1) void k_out_mlp(
    const float* __restrict__ x,
    const float* __restrict__ w1, const float* __restrict__ b1,
    const float* __restrict__ w2, const float* __restrict__ b2,
    float* __restrict__ out)
{
    extern __shared__ float sm[];
    float* xs  = sm;               // 256*64 tile (x, agg, then h)
    float* w1t = xs + 256 * 64;    // 8192 (128 k-rows, pair-interleaved)
    float* w2t = w1t + 8192;       // 4096

    const int tid = threadIdx.x;
    const int n0  = blockIdx.x * 256;
    const int lane = tid & 31, warp = tid >> 5;
    const int r0 = (warp & 7) * 32 + (lane >> 3) * 8;
    const int c0 = (warp >> 3) * 32 + (lane & 7) * 4;
    const int j0 = c0 >> 1;
    const int pc0 = wperm(j0) * 4, pc1 = wperm(j0 + 1) * 4;

    stage_w(w1t, w1, 128, tid);
    stage_w(w2t, w2, 64, tid);
    stage_tile(xs, (const float4*)(x + (size_t)n0 * D), n0, tid);
    __syncthreads();

    u64t acc[8][4];
    zero_acc(acc);
    sweep(acc, xs, w1t, r0, pc0, pc1);          // k = 0..63 (x part)
    __syncthreads();                             // x-tile reads done

    stage_tile(xs, (const float4*)(g_agg4 + (size_t)n0 * (D / 4)), n0, tid);
    __syncthreads();
    sweep(acc, xs, w1t + 4096, r0, pc0, pc1);   // k = 64..127 (agg part)
    __syncthreads();                             // agg-tile reads done
    finalize_relu_tile(xs, acc, b1, r0, c0);
    __syncthreads();

    zero_acc(acc);
    sweep(acc, xs, w2t, r0, pc0, pc1);
    finalize_store(out, acc, b2, n0, r0, c0);
}

// ---------------------------------------------------------------------------
// Launch. Inputs: 0 x, 1 edge_index, 2 batch, 3..6 msg mlp, 7..10 out mlp
// ---------------------------------------------------------------------------
extern "C" void kernel_launch(void* const* d_in, const int* in_sizes, int n_in,
                              void* d_out, int out_size)
{
    const float* x      = (const float*)d_in[0];
    const void*  ei     = d_in[1];
    const float* msg_w1 = (const float*)d_in[3];
    const float* msg_b1 = (const float*)d_in[4];
    const float* msg_w2 = (const float*)d_in[5];
    const float* msg_b2 = (const float*)d_in[6];
    const float* out_w1 = (const float*)d_in[7];
    const float* out_b1 = (const float*)d_in[8];
    const float* out_w2 = (const float*)d_in[9];
    const float* out_b2 = (const float*)d_in[10];
    float*       out    = (float*)d_out;

    const int smem1 = K1_SMEM_FLOATS * sizeof(float);   // 96 KB
    const int smem3 = K3_SMEM_FLOATS * sizeof(float);   // 112 KB
    cudaFuncSetAttribute(k_msg_mlp, cudaFuncAttributeMaxDynamicSharedMemorySize, smem1);
    cudaFuncSetAttribute(k_out_mlp, cudaFuncAttributeMaxDynamicSharedMemorySize, smem3);

    const int nodeBlocks = (N_NODES + 255) / 256;   // 391

    k_zero_agg<<<(N_NODES * D / 4 + 255) / 256, 256>>>((const int*)ei);
    k_msg_mlp<<<nodeBlocks, 512, smem1>>>(x, msg_w1, msg_b1, msg_w2, msg_b2);
    {
        long long work = (long long)N_EDGES * 16;
        int blocks = (int)((work + 255) / 256);
        k_scatter<<<blocks, 256>>>(ei);
    }
    k_out_mlp<<<nodeBlocks, 512, smem3>>>(x, out_w1, out_b1, out_w2, out_b2, out);
}

// round 8
// speedup vs baseline: 1.4551x; 1.4551x over previous
#include <cuda_runtime.h>
#include <cstdint>

#define N_NODES 100000
#define N_EDGES 1000000
#define D 64

// Scratch: device globals (no allocs allowed). float4 => 16B aligned.
__device__ float4 g_y4[(size_t)N_NODES * (D / 4)];    // message MLP output
__device__ float4 g_agg4[(size_t)N_NODES * (D / 4)];  // scatter-sum accumulator
__device__ int    g_ei_is64;                          // 1 if edge_index is int64

// fp32 -> tf32 (round-to-nearest-away), kept in a 32-bit register/float slot.
__device__ __forceinline__ uint32_t f2tf(float f) {
    uint32_t r; asm("cvt.rna.tf32.f32 %0, %1;" : "=r"(r) : "f"(f)); return r;
}
__device__ __forceinline__ float f2tff(float f) { return __uint_as_float(f2tf(f)); }

// ---------------------------------------------------------------------------
// K0: zero agg + detect edge_index dtype (int64 LE => odd 32-bit words == 0)
// ---------------------------------------------------------------------------
__global__ void k_zero_agg(const int* __restrict__ ei32) {
    int idx = blockIdx.x * blockDim.x + threadIdx.x;
    const int n4 = N_NODES * (D / 4);
    if (idx < n4) g_agg4[idx] = make_float4(0.f, 0.f, 0.f, 0.f);
    if (blockIdx.x == 0 && threadIdx.x == 0) {
        int is64 = 1;
        for (int i = 0; i < 64; i++)
            if (ei32[2 * i + 1] != 0) { is64 = 0; break; }
        g_ei_is64 = is64;
    }
}

// ---------------------------------------------------------------------------
// Tensor-core MLP building blocks.
// CTA = 512 threads (16 warps); tile = 256 rows x 64 cols, pitch 68 floats
// (pitch 68 => A-frag lanes hit banks (4g+tig)%32: conflict-free).
// Warp w owns rows [16w, 16w+16) and all 64 cols: accums = 8 mma tiles x 4.
// Weights in smem row-major [k][c] with col swizzle c ^ 8*(k&3): B-frag
// lanes (g,tig) read 32 distinct banks.
// mma.m16n8k8 fragments (lane: g=lane>>2, tig=lane&3):
//   A: a0=(g, tig) a1=(g+8, tig) a2=(g, tig+4) a3=(g+8, tig+4)   [row, k]
//   B: b0=(tig, g) b1=(tig+4, g)                                  [k, col]
//   C: c0=(g, 2tig) c1=(g, 2tig+1) c2=(g+8, 2tig) c3=(g+8, 2tig+1)
// ---------------------------------------------------------------------------
#define PITCH 68

// Stage 256x64 gmem slab into pitch-68 tile, tf32-rounded, zero-padded.
__device__ __forceinline__ void stage_tile(float* xs, const float4* src4,
                                           int n0, int tid) {
#pragma unroll
    for (int it = 0; it < 8; it++) {
        int i = tid + it * 512;                 // float4 index, 4096 total
        int l = i >> 4, kq = i & 15;
        float4 v = make_float4(0.f, 0.f, 0.f, 0.f);
        if (n0 + l < N_NODES) v = src4[i];
        v.x = f2tff(v.x); v.y = f2tff(v.y); v.z = f2tff(v.z); v.w = f2tff(v.w);
        *(float4*)(xs + l * PITCH + 4 * kq) = v;
    }
}

// Stage Krows x 64 weights, tf32-rounded, with the XOR bank swizzle.
__device__ __forceinline__ void stage_w(float* ws, const float* __restrict__ w,
                                        int Krows, int tid) {
    for (int idx = tid; idx < Krows * 64; idx += 512) {
        int k = idx >> 6, c = idx & 63;
        ws[k * 64 + (c ^ (8 * (k & 3)))] = f2tff(w[idx]);
    }
}

// acc += tile[r0..r0+15][0..64) @ W[0..64)[0..64)
__device__ __forceinline__ void mma_sweep(float acc[8][4], const float* xs,
                                          const float* ws, int r0, int g, int tig) {
#pragma unroll
    for (int s = 0; s < 8; s++) {
        const int k0 = 8 * s;
        const float* xr0 = xs + (r0 + g) * PITCH + k0 + tig;
        const float* xr8 = xs + (r0 + 8 + g) * PITCH + k0 + tig;
        uint32_t a0 = __float_as_uint(xr0[0]);
        uint32_t a1 = __float_as_uint(xr8[0]);
        uint32_t a2 = __float_as_uint(xr0[4]);
        uint32_t a3 = __float_as_uint(xr8[4]);
        const float* w0 = ws + (k0 + tig) * 64;
        const float* w4 = ws + (k0 + 4 + tig) * 64;
        const int xm = 8 * tig;
#pragma unroll
        for (int t = 0; t < 8; t++) {
            int c = (8 * t + g) ^ xm;
            uint32_t b0 = __float_as_uint(w0[c]);
            uint32_t b1 = __float_as_uint(w4[c]);
            asm volatile(
                "mma.sync.aligned.m16n8k8.row.col.f32.tf32.tf32.f32 "
                "{%0,%1,%2,%3}, {%4,%5,%6,%7}, {%8,%9}, {%0,%1,%2,%3};"
                : "+f"(acc[t][0]), "+f"(acc[t][1]), "+f"(acc[t][2]), "+f"(acc[t][3])
                : "r"(a0), "r"(a1), "r"(a2), "r"(a3), "r"(b0), "r"(b1));
        }
    }
}

__device__ __forceinline__ void zero_acc(float acc[8][4]) {
#pragma unroll
    for (int t = 0; t < 8; t++)
#pragma unroll
        for (int p = 0; p < 4; p++) acc[t][p] = 0.f;
}

// relu(acc+bias), tf32-round, write back into the tile (warp-own rows).
__device__ __forceinline__ void write_h(float* xs, float acc[8][4],
                                        const float* __restrict__ bias,
                                        int r0, int g, int tig) {
#pragma unroll
    for (int t = 0; t < 8; t++) {
        int c = 8 * t + 2 * tig;
        float b0 = __ldg(bias + c), b1 = __ldg(bias + c + 1);
        float2 lo, hi;
        lo.x = f2tff(fmaxf(acc[t][0] + b0, 0.f));
        lo.y = f2tff(fmaxf(acc[t][1] + b1, 0.f));
        hi.x = f2tff(fmaxf(acc[t][2] + b0, 0.f));
        hi.y = f2tff(fmaxf(acc[t][3] + b1, 0.f));
        *(float2*)(xs + (r0 + g) * PITCH + c)     = lo;
        *(float2*)(xs + (r0 + 8 + g) * PITCH + c) = hi;
    }
}

// acc+bias -> gmem (guarded), float2 per mma tile-row.
__device__ __forceinline__ void store_out(float* dst, float acc[8][4],
                                          const float* __restrict__ bias,
                                          int n0, int r0, int g, int tig) {
    int nlo = n0 + r0 + g, nhi = nlo + 8;
    bool oklo = nlo < N_NODES, okhi = nhi < N_NODES;
#pragma unroll
    for (int t = 0; t < 8; t++) {
        int c = 8 * t + 2 * tig;
        float b0 = __ldg(bias + c), b1 = __ldg(bias + c + 1);
        if (oklo) {
            float2 v; v.x = acc[t][0] + b0; v.y = acc[t][1] + b1;
            *(float2*)(dst + (size_t)nlo * D + c) = v;
        }
        if (okhi) {
            float2 v; v.x = acc[t][2] + b0; v.y = acc[t][3] + b1;
            *(float2*)(dst + (size_t)nhi * D + c) = v;
        }
    }
}

// ---------------------------------------------------------------------------
// K1: node message MLP  y = relu(x @ W1 + b1) @ W2 + b2      [N,64]
// ---------------------------------------------------------------------------
#define K1_SMEM_FLOATS (256 * PITCH + 4096 + 4096)

__global__ __launch_bounds__(512) void k_msg_mlp(
    const float* __restrict__ x,
    const float* __restrict__ w1, const float* __restrict__ b1,
    const float* __restrict__ w2, const float* __restrict__ b2)
{
    extern __shared__ float sm[];
    float* xs  = sm;                  // 256*68 tile (x, then h)
    float* w1t = xs + 256 * PITCH;    // 4096
    float* w2t = w1t + 4096;          // 4096

    const int tid = threadIdx.x;
    const int n0  = blockIdx.x * 256;
    const int lane = tid & 31, warp = tid >> 5;
    const int g = lane >> 2, tig = lane & 3;
    const int r0 = warp * 16;

    stage_w(w1t, w1, 64, tid);
    stage_w(w2t, w2, 64, tid);
    stage_tile(xs, (const float4*)(x + (size_t)n0 * D), n0, tid);
    __syncthreads();

    float acc[8][4];
    zero_acc(acc);
    mma_sweep(acc, xs, w1t, r0, g, tig);   // reads only warp-own rows
    __syncwarp();
    write_h(xs, acc, b1, r0, g, tig);      // writes only warp-own rows
    __syncwarp();

    zero_acc(acc);
    mma_sweep(acc, xs, w2t, r0, g, tig);
    store_out((float*)g_y4, acc, b2, n0, r0, g, tig);
}

// ---------------------------------------------------------------------------
// K2: scatter  agg[col] += y[row]  via red.global.add.v4.f32
// ---------------------------------------------------------------------------
__global__ __launch_bounds__(256) void k_scatter(const void* __restrict__ ei_raw)
{
    long long tid = (long long)blockIdx.x * blockDim.x + threadIdx.x;
    if (tid >= (long long)N_EDGES * 16) return;
    int e = (int)(tid >> 4);
    int c = (int)(tid & 15);

    int row, col;
    if (g_ei_is64) {
        const long long* ei = (const long long*)ei_raw;
        row = (int)ei[e];
        col = (int)ei[N_EDGES + e];
    } else {
        const int* ei = (const int*)ei_raw;
        row = ei[e];
        col = ei[N_EDGES + e];
    }
    if ((unsigned)row >= N_NODES || (unsigned)col >= N_NODES) return;

    const float4 v = g_y4[(size_t)row * (D / 4) + c];
    float4* p = g_agg4 + (size_t)col * (D / 4) + c;
    asm volatile("red.global.add.v4.f32 [%0], {%1,%2,%3,%4};"
                 :: "l"(p), "f"(v.x), "f"(v.y), "f"(v.z), "f"(v.w)
                 : "memory");
}

// ---------------------------------------------------------------------------
// K3: output MLP  out = relu([x,agg] @ W1 + b1) @ W2 + b2     [N,64]
// Two-pass layer 1: x tile vs W1[0:64], restage agg tile, vs W1[64:128].
// ---------------------------------------------------------------------------
#define K3_SMEM_FLOATS (256 * PITCH + 8192 + 4096)

__global__ __launch_bounds__(512) void k_out_mlp(
    const float* __restrict__ x,
    const float* __restrict__ w1, const float* __restrict__ b1,
    const float* __restrict__ w2, const float* __restrict__ b2,
    float* __restrict__ out)
{
    extern __shared__ float sm[];
    float* xs  = sm;                  // 256*68 tile (x, agg, then h)
    float* w1t = xs + 256 * PITCH;    // 8192 (128 k-rows)
    float* w2t = w1t + 8192;          // 4096

    const int tid = threadIdx.x;
    const int n0  = blockIdx.x * 256;
    const int lane = tid & 31, warp = tid >> 5;
    const int g = lane >> 2, tig = lane & 3;
    const int r0 = warp * 16;

    stage_w(w1t, w1, 128, tid);
    stage_w(w2t, w2, 64, tid);
    stage_tile(xs, (const float4*)(x + (size_t)n0 * D), n0, tid);
    __syncthreads();

    float acc[8][4];
    zero_acc(acc);
    mma_sweep(acc, xs, w1t, r0, g, tig);            // k = 0..63 (x)
    __syncthreads();                                 // all x-tile reads done

    stage_tile(xs, (const float4*)(g_agg4 + (size_t)n0 * (D / 4)), n0, tid);
    __syncthreads();
    mma_sweep(acc, xs, w1t + 64 * 64, r0, g, tig);  // k = 64..127 (agg)
    __syncwarp();
    write_h(xs, acc, b1, r0, g, tig);
    __syncwarp();

    zero_acc(acc);
    mma_sweep(acc, xs, w2t, r0, g, tig);
    store_out(out, acc, b2, n0, r0, g, tig);
}

// ---------------------------------------------------------------------------
// Launch. Inputs: 0 x, 1 edge_index, 2 batch, 3..6 msg mlp, 7..10 out mlp
// ---------------------------------------------------------------------------
extern "C" void kernel_launch(void* const* d_in, const int* in_sizes, int n_in,
                              void* d_out, int out_size)
{
    const float* x      = (const float*)d_in[0];
    const void*  ei     = d_in[1];
    const float* msg_w1 = (const float*)d_in[3];
    const float* msg_b1 = (const float*)d_in[4];
    const float* msg_w2 = (const float*)d_in[5];
    const float* msg_b2 = (const float*)d_in[6];
    const float* out_w1 = (const float*)d_in[7];
    const float* out_b1 = (const float*)d_in[8];
    const float* out_w2 = (const float*)d_in[9];
    const float* out_b2 = (const float*)d_in[10];
    float*       out    = (float*)d_out;

    const int smem1 = K1_SMEM_FLOATS * sizeof(float);   // ~100 KB
    const int smem3 = K3_SMEM_FLOATS * sizeof(float);   // ~116 KB
    cudaFuncSetAttribute(k_msg_mlp, cudaFuncAttributeMaxDynamicSharedMemorySize, smem1);
    cudaFuncSetAttribute(k_out_mlp, cudaFuncAttributeMaxDynamicSharedMemorySize, smem3);

    const int nodeBlocks = (N_NODES + 255) / 256;   // 391

    k_zero_agg<<<(N_NODES * D / 4 + 255) / 256, 256>>>((const int*)ei);
    k_msg_mlp<<<nodeBlocks, 512, smem1>>>(x, msg_w1, msg_b1, msg_w2, msg_b2);
    {
        long long work = (long long)N_EDGES * 16;
        int blocks = (int)((work + 255) / 256);
        k_scatter<<<blocks, 256>>>(ei);
    }
    k_out_mlp<<<nodeBlocks, 512, smem3>>>(x, out_w1, out_b1, out_w2, out_b2, out);
}

// round 9
// speedup vs baseline: 1.6341x; 1.1230x over previous
#include <cuda_runtime.h>
#include <cstdint>

#define N_NODES 100000
#define N_EDGES 1000000
#define D 64

// Scratch: device globals (no allocs allowed). float4 => 16B aligned.
__device__ float4 g_y4[(size_t)N_NODES * (D / 4)];    // message MLP output
__device__ float4 g_agg4[(size_t)N_NODES * (D / 4)];  // scatter-sum accumulator
__device__ int    g_ei_is64;                          // 1 if edge_index is int64

// fp32 -> tf32 (round-to-nearest-away), kept in a 32-bit float slot.
__device__ __forceinline__ uint32_t f2tf(float f) {
    uint32_t r; asm("cvt.rna.tf32.f32 %0, %1;" : "=r"(r) : "f"(f)); return r;
}
__device__ __forceinline__ float f2tff(float f) { return __uint_as_float(f2tf(f)); }

// ---------------------------------------------------------------------------
// Tensor-core MLP building blocks.
// CTA = 256 threads (8 warps); tile = 128 rows x 64 cols, pitch 68 floats
// (A-frag lanes hit banks (4g+tig)%32: conflict-free).
// Warp w owns rows [16w, 16w+16) x all 64 cols: 8 mma tiles of m16n8k8.
// Weights in smem row-major [k][c] with col swizzle c ^ 8*(k&3).
// ---------------------------------------------------------------------------
#define PITCH 68
#define TROWS 128

// Stage 128x64 gmem slab into pitch-68 tile, tf32-rounded, zero-padded.
__device__ __forceinline__ void stage_tile(float* xs, const float4* src4,
                                           int n0, int tid) {
#pragma unroll
    for (int it = 0; it < 8; it++) {
        int i = tid + it * 256;                 // float4 index, 2048 total
        int l = i >> 4, kq = i & 15;
        float4 v = make_float4(0.f, 0.f, 0.f, 0.f);
        if (n0 + l < N_NODES) v = src4[i];
        v.x = f2tff(v.x); v.y = f2tff(v.y); v.z = f2tff(v.z); v.w = f2tff(v.w);
        *(float4*)(xs + l * PITCH + 4 * kq) = v;
    }
}

// Stage Krows x 64 weights (float4 path), tf32-rounded, XOR bank swizzle.
// The swizzle XORs multiples of 8 onto the column => 4-aligned blocks stay intact.
__device__ __forceinline__ void stage_w(float* ws, const float* __restrict__ w,
                                        int Krows, int tid) {
    const float4* w4 = (const float4*)w;
    for (int i = tid; i < Krows * 16; i += 256) {
        int k = i >> 4, c0 = (i & 15) * 4;
        float4 v = w4[i];
        v.x = f2tff(v.x); v.y = f2tff(v.y); v.z = f2tff(v.z); v.w = f2tff(v.w);
        *(float4*)(ws + k * 64 + (c0 ^ (8 * (k & 3)))) = v;
    }
}

// acc += tile[r0..r0+15][0..64) @ W[0..64)[0..64)
__device__ __forceinline__ void mma_sweep(float acc[8][4], const float* xs,
                                          const float* ws, int r0, int g, int tig) {
#pragma unroll
    for (int s = 0; s < 8; s++) {
        const int k0 = 8 * s;
        const float* xr0 = xs + (r0 + g) * PITCH + k0 + tig;
        const float* xr8 = xs + (r0 + 8 + g) * PITCH + k0 + tig;
        uint32_t a0 = __float_as_uint(xr0[0]);
        uint32_t a1 = __float_as_uint(xr8[0]);
        uint32_t a2 = __float_as_uint(xr0[4]);
        uint32_t a3 = __float_as_uint(xr8[4]);
        const float* w0 = ws + (k0 + tig) * 64;
        const float* w4 = ws + (k0 + 4 + tig) * 64;
        const int xm = 8 * tig;
#pragma unroll
        for (int t = 0; t < 8; t++) {
            int c = (8 * t + g) ^ xm;
            uint32_t b0 = __float_as_uint(w0[c]);
            uint32_t b1 = __float_as_uint(w4[c]);
            asm volatile(
                "mma.sync.aligned.m16n8k8.row.col.f32.tf32.tf32.f32 "
                "{%0,%1,%2,%3}, {%4,%5,%6,%7}, {%8,%9}, {%0,%1,%2,%3};"
                : "+f"(acc[t][0]), "+f"(acc[t][1]), "+f"(acc[t][2]), "+f"(acc[t][3])
                : "r"(a0), "r"(a1), "r"(a2), "r"(a3), "r"(b0), "r"(b1));
        }
    }
}

__device__ __forceinline__ void zero_acc(float acc[8][4]) {
#pragma unroll
    for (int t = 0; t < 8; t++)
#pragma unroll
        for (int p = 0; p < 4; p++) acc[t][p] = 0.f;
}

// relu(acc+bias), tf32-round, write back into the tile (warp-own rows).
__device__ __forceinline__ void write_h(float* xs, float acc[8][4],
                                        const float* __restrict__ bias,
                                        int r0, int g, int tig) {
#pragma unroll
    for (int t = 0; t < 8; t++) {
        int c = 8 * t + 2 * tig;
        float b0 = __ldg(bias + c), b1 = __ldg(bias + c + 1);
        float2 lo, hi;
        lo.x = f2tff(fmaxf(acc[t][0] + b0, 0.f));
        lo.y = f2tff(fmaxf(acc[t][1] + b1, 0.f));
        hi.x = f2tff(fmaxf(acc[t][2] + b0, 0.f));
        hi.y = f2tff(fmaxf(acc[t][3] + b1, 0.f));
        *(float2*)(xs + (r0 + g) * PITCH + c)     = lo;
        *(float2*)(xs + (r0 + 8 + g) * PITCH + c) = hi;
    }
}

// acc+bias -> gmem (guarded), float2 per mma tile-row.
__device__ __forceinline__ void store_out(float* dst, float acc[8][4],
                                          const float* __restrict__ bias,
                                          int n0, int r0, int g, int tig) {
    int nlo = n0 + r0 + g, nhi = nlo + 8;
    bool oklo = nlo < N_NODES, okhi = nhi < N_NODES;
#pragma unroll
    for (int t = 0; t < 8; t++) {
        int c = 8 * t + 2 * tig;
        float b0 = __ldg(bias + c), b1 = __ldg(bias + c + 1);
        if (oklo) {
            float2 v; v.x = acc[t][0] + b0; v.y = acc[t][1] + b1;
            *(float2*)(dst + (size_t)nlo * D + c) = v;
        }
        if (okhi) {
            float2 v; v.x = acc[t][2] + b0; v.y = acc[t][3] + b1;
            *(float2*)(dst + (size_t)nhi * D + c) = v;
        }
    }
}

// ---------------------------------------------------------------------------
// K1: node message MLP  y = relu(x @ W1 + b1) @ W2 + b2      [N,64]
// Also zeroes this block's slice of g_agg (for the later scatter) and, in
// block 0, detects the edge_index dtype. 66KB smem -> 3 CTAs/SM.
// ---------------------------------------------------------------------------
#define K1_SMEM_FLOATS (TROWS * PITCH + 4096 + 4096)

__global__ __launch_bounds__(256) void k_msg_mlp(
    const float* __restrict__ x,
    const float* __restrict__ w1, const float* __restrict__ b1,
    const float* __restrict__ w2, const float* __restrict__ b2,
    const int* __restrict__ ei32)
{
    extern __shared__ float sm[];
    float* xs  = sm;                    // 128*68 tile (x, then h)
    float* w1t = xs + TROWS * PITCH;    // 4096
    float* w2t = w1t + 4096;            // 4096

    const int tid = threadIdx.x;
    const int n0  = blockIdx.x * TROWS;
    const int lane = tid & 31, warp = tid >> 5;
    const int g = lane >> 2, tig = lane & 3;
    const int r0 = warp * 16;

    // Zero this block's g_agg slice (scatter runs after this kernel).
    {
        float4 z = make_float4(0.f, 0.f, 0.f, 0.f);
#pragma unroll
        for (int it = 0; it < 8; it++) {
            int i = n0 * 16 + tid + it * 256;
            if (i < N_NODES * 16) g_agg4[i] = z;
        }
    }
    if (blockIdx.x == 0 && tid == 0) {
        int is64 = 1;
        for (int i = 0; i < 64; i++)
            if (ei32[2 * i + 1] != 0) { is64 = 0; break; }
        g_ei_is64 = is64;
    }

    stage_w(w1t, w1, 64, tid);
    stage_w(w2t, w2, 64, tid);
    stage_tile(xs, (const float4*)(x + (size_t)n0 * D), n0, tid);
    __syncthreads();

    float acc[8][4];
    zero_acc(acc);
    mma_sweep(acc, xs, w1t, r0, g, tig);   // reads only warp-own rows
    __syncwarp();
    write_h(xs, acc, b1, r0, g, tig);      // writes only warp-own rows
    __syncwarp();

    zero_acc(acc);
    mma_sweep(acc, xs, w2t, r0, g, tig);
    store_out((float*)g_y4, acc, b2, n0, r0, g, tig);
}

// ---------------------------------------------------------------------------
// K2: scatter  agg[col] += y[row]  via red.global.add.v4.f32
// ---------------------------------------------------------------------------
__global__ __launch_bounds__(256) void k_scatter(const void* __restrict__ ei_raw)
{
    long long tid = (long long)blockIdx.x * blockDim.x + threadIdx.x;
    if (tid >= (long long)N_EDGES * 16) return;
    int e = (int)(tid >> 4);
    int c = (int)(tid & 15);

    int row, col;
    if (g_ei_is64) {
        const long long* ei = (const long long*)ei_raw;
        row = (int)ei[e];
        col = (int)ei[N_EDGES + e];
    } else {
        const int* ei = (const int*)ei_raw;
        row = ei[e];
        col = ei[N_EDGES + e];
    }
    if ((unsigned)row >= N_NODES || (unsigned)col >= N_NODES) return;

    const float4 v = g_y4[(size_t)row * (D / 4) + c];
    float4* p = g_agg4 + (size_t)col * (D / 4) + c;
    asm volatile("red.global.add.v4.f32 [%0], {%1,%2,%3,%4};"
                 :: "l"(p), "f"(v.x), "f"(v.y), "f"(v.z), "f"(v.w)
                 : "memory");
}

// ---------------------------------------------------------------------------
// K3: output MLP  out = relu([x,agg] @ W1 + b1) @ W2 + b2     [N,64]
// Two-pass layer 1: x tile vs W1[0:64], restage agg tile, vs W1[64:128].
// 82KB smem -> 2 CTAs/SM.
// ---------------------------------------------------------------------------
#define K3_SMEM_FLOATS (TROWS * PITCH + 8192 + 4096)

__global__ __launch_bounds__(256) void k_out_mlp(
    const float* __restrict__ x,
    const float* __restrict__ w1, const float* __restrict__ b1,
    const float* __restrict__ w2, const float* __restrict__ b2,
    float* __restrict__ out)
{
    extern __shared__ float sm[];
    float* xs  = sm;                    // 128*68 tile (x, agg, then h)
    float* w1t = xs + TROWS * PITCH;    // 8192 (128 k-rows)
    float* w2t = w1t + 8192;            // 4096

    const int tid = threadIdx.x;
    const int n0  = blockIdx.x * TROWS;
    const int lane = tid & 31, warp = tid >> 5;
    const int g = lane >> 2, tig = lane & 3;
    const int r0 = warp * 16;

    stage_w(w1t, w1, 128, tid);
    stage_w(w2t, w2, 64, tid);
    stage_tile(xs, (const float4*)(x + (size_t)n0 * D), n0, tid);
    __syncthreads();

    float acc[8][4];
    zero_acc(acc);
    mma_sweep(acc, xs, w1t, r0, g, tig);            // k = 0..63 (x)
    __syncthreads();                                 // all x-tile reads done

    stage_tile(xs, (const float4*)(g_agg4 + (size_t)n0 * (D / 4)), n0, tid);
    __syncthreads();
    mma_sweep(acc, xs, w1t + 64 * 64, r0, g, tig);  // k = 64..127 (agg)
    __syncwarp();
    write_h(xs, acc, b1, r0, g, tig);
    __syncwarp();

    zero_acc(acc);
    mma_sweep(acc, xs, w2t, r0, g, tig);
    store_out(out, acc, b2, n0, r0, g, tig);
}

// ---------------------------------------------------------------------------
// Launch. Inputs: 0 x, 1 edge_index, 2 batch, 3..6 msg mlp, 7..10 out mlp
// ---------------------------------------------------------------------------
extern "C" void kernel_launch(void* const* d_in, const int* in_sizes, int n_in,
                              void* d_out, int out_size)
{
    const float* x      = (const float*)d_in[0];
    const void*  ei     = d_in[1];
    const float* msg_w1 = (const float*)d_in[3];
    const float* msg_b1 = (const float*)d_in[4];
    const float* msg_w2 = (const float*)d_in[5];
    const float* msg_b2 = (const float*)d_in[6];
    const float* out_w1 = (const float*)d_in[7];
    const float* out_b1 = (const float*)d_in[8];
    const float* out_w2 = (const float*)d_in[9];
    const float* out_b2 = (const float*)d_in[10];
    float*       out    = (float*)d_out;

    const int smem1 = K1_SMEM_FLOATS * sizeof(float);   // ~66 KB
    const int smem3 = K3_SMEM_FLOATS * sizeof(float);   // ~82 KB
    cudaFuncSetAttribute(k_msg_mlp, cudaFuncAttributeMaxDynamicSharedMemorySize, smem1);
    cudaFuncSetAttribute(k_out_mlp, cudaFuncAttributeMaxDynamicSharedMemorySize, smem3);

    const int nodeBlocks = (N_NODES + TROWS - 1) / TROWS;   // 782

    k_msg_mlp<<<nodeBlocks, 256, smem1>>>(x, msg_w1, msg_b1, msg_w2, msg_b2,
                                          (const int*)ei);
    {
        long long work = (long long)N_EDGES * 16;
        int blocks = (int)((work + 255) / 256);
        k_scatter<<<blocks, 256>>>(ei);
    }
    k_out_mlp<<<nodeBlocks, 256, smem3>>>(x, out_w1, out_b1, out_w2, out_b2, out);
}

// round 10
// speedup vs baseline: 1.7120x; 1.0476x over previous
#include <cuda_runtime.h>
#include <cuda_fp16.h>
#include <cstdint>

#define N_NODES 100000
#define N_EDGES 1000000
#define D 64

// Scratch: device globals (no allocs allowed).
__device__ uint2  g_yh[(size_t)N_NODES * 16];         // message MLP output, fp16 (64 halves/row)
__device__ float4 g_agg4[(size_t)N_NODES * (D / 4)];  // scatter-sum accumulator (f32)
__device__ int    g_ei_is64;                          // 1 if edge_index is int64

// fp32 -> tf32 (round-to-nearest-away), kept in a 32-bit float slot.
__device__ __forceinline__ uint32_t f2tf(float f) {
    uint32_t r; asm("cvt.rna.tf32.f32 %0, %1;" : "=r"(r) : "f"(f)); return r;
}
__device__ __forceinline__ float f2tff(float f) { return __uint_as_float(f2tf(f)); }

// ---------------------------------------------------------------------------
// Tensor-core MLP building blocks.
// CTA = 256 threads (8 warps); tile = 128 rows x 64 cols, pitch 68 floats
// (A-frag lanes hit banks (4g+tig)%32: conflict-free).
// Warp w owns rows [16w, 16w+16) x all 64 cols: 8 mma tiles of m16n8k8.
// Weights in smem row-major [k][c] with col swizzle c ^ 8*(k&3).
// ---------------------------------------------------------------------------
#define PITCH 68
#define TROWS 128

// Stage 128x64 gmem slab into pitch-68 tile, tf32-rounded, zero-padded.
__device__ __forceinline__ void stage_tile(float* xs, const float4* src4,
                                           int n0, int tid) {
#pragma unroll
    for (int it = 0; it < 8; it++) {
        int i = tid + it * 256;                 // float4 index, 2048 total
        int l = i >> 4, kq = i & 15;
        float4 v = make_float4(0.f, 0.f, 0.f, 0.f);
        if (n0 + l < N_NODES) v = src4[i];
        v.x = f2tff(v.x); v.y = f2tff(v.y); v.z = f2tff(v.z); v.w = f2tff(v.w);
        *(float4*)(xs + l * PITCH + 4 * kq) = v;
    }
}

// Stage Krows x 64 weights (float4 path), tf32-rounded, XOR bank swizzle.
__device__ __forceinline__ void stage_w(float* ws, const float* __restrict__ w,
                                        int Krows, int tid) {
    const float4* w4 = (const float4*)w;
    for (int i = tid; i < Krows * 16; i += 256) {
        int k = i >> 4, c0 = (i & 15) * 4;
        float4 v = w4[i];
        v.x = f2tff(v.x); v.y = f2tff(v.y); v.z = f2tff(v.z); v.w = f2tff(v.w);
        *(float4*)(ws + k * 64 + (c0 ^ (8 * (k & 3)))) = v;
    }
}

// acc += tile[r0..r0+15][0..64) @ W[0..64)[0..64)
__device__ __forceinline__ void mma_sweep(float acc[8][4], const float* xs,
                                          const float* ws, int r0, int g, int tig) {
#pragma unroll
    for (int s = 0; s < 8; s++) {
        const int k0 = 8 * s;
        const float* xr0 = xs + (r0 + g) * PITCH + k0 + tig;
        const float* xr8 = xs + (r0 + 8 + g) * PITCH + k0 + tig;
        uint32_t a0 = __float_as_uint(xr0[0]);
        uint32_t a1 = __float_as_uint(xr8[0]);
        uint32_t a2 = __float_as_uint(xr0[4]);
        uint32_t a3 = __float_as_uint(xr8[4]);
        const float* w0 = ws + (k0 + tig) * 64;
        const float* w4 = ws + (k0 + 4 + tig) * 64;
        const int xm = 8 * tig;
#pragma unroll
        for (int t = 0; t < 8; t++) {
            int c = (8 * t + g) ^ xm;
            uint32_t b0 = __float_as_uint(w0[c]);
            uint32_t b1 = __float_as_uint(w4[c]);
            asm volatile(
                "mma.sync.aligned.m16n8k8.row.col.f32.tf32.tf32.f32 "
                "{%0,%1,%2,%3}, {%4,%5,%6,%7}, {%8,%9}, {%0,%1,%2,%3};"
                : "+f"(acc[t][0]), "+f"(acc[t][1]), "+f"(acc[t][2]), "+f"(acc[t][3])
                : "r"(a0), "r"(a1), "r"(a2), "r"(a3), "r"(b0), "r"(b1));
        }
    }
}

__device__ __forceinline__ void zero_acc(float acc[8][4]) {
#pragma unroll
    for (int t = 0; t < 8; t++)
#pragma unroll
        for (int p = 0; p < 4; p++) acc[t][p] = 0.f;
}

// relu(acc+bias), tf32-round, write back into the tile (warp-own rows).
__device__ __forceinline__ void write_h(float* xs, float acc[8][4],
                                        const float* __restrict__ bias,
                                        int r0, int g, int tig) {
#pragma unroll
    for (int t = 0; t < 8; t++) {
        int c = 8 * t + 2 * tig;
        float b0 = __ldg(bias + c), b1 = __ldg(bias + c + 1);
        float2 lo, hi;
        lo.x = f2tff(fmaxf(acc[t][0] + b0, 0.f));
        lo.y = f2tff(fmaxf(acc[t][1] + b1, 0.f));
        hi.x = f2tff(fmaxf(acc[t][2] + b0, 0.f));
        hi.y = f2tff(fmaxf(acc[t][3] + b1, 0.f));
        *(float2*)(xs + (r0 + g) * PITCH + c)     = lo;
        *(float2*)(xs + (r0 + 8 + g) * PITCH + c) = hi;
    }
}

// acc+bias -> f32 gmem (guarded), float2 per mma tile-row.
__device__ __forceinline__ void store_out(float* dst, float acc[8][4],
                                          const float* __restrict__ bias,
                                          int n0, int r0, int g, int tig) {
    int nlo = n0 + r0 + g, nhi = nlo + 8;
    bool oklo = nlo < N_NODES, okhi = nhi < N_NODES;
#pragma unroll
    for (int t = 0; t < 8; t++) {
        int c = 8 * t + 2 * tig;
        float b0 = __ldg(bias + c), b1 = __ldg(bias + c + 1);
        if (oklo) {
            float2 v; v.x = acc[t][0] + b0; v.y = acc[t][1] + b1;
            *(float2*)(dst + (size_t)nlo * D + c) = v;
        }
        if (okhi) {
            float2 v; v.x = acc[t][2] + b0; v.y = acc[t][3] + b1;
            *(float2*)(dst + (size_t)nhi * D + c) = v;
        }
    }
}

// acc+bias -> fp16 y buffer (guarded), one half2 (4B) per mma tile-row.
__device__ __forceinline__ void store_out_h(float acc[8][4],
                                            const float* __restrict__ bias,
                                            int n0, int r0, int g, int tig) {
    uint32_t* yh = (uint32_t*)g_yh;   // 32 uints per row
    int nlo = n0 + r0 + g, nhi = nlo + 8;
    bool oklo = nlo < N_NODES, okhi = nhi < N_NODES;
#pragma unroll
    for (int t = 0; t < 8; t++) {
        int c = 8 * t + 2 * tig;
        float b0 = __ldg(bias + c), b1 = __ldg(bias + c + 1);
        if (oklo) {
            __half2 v = __floats2half2_rn(acc[t][0] + b0, acc[t][1] + b1);
            yh[nlo * 32 + (c >> 1)] = *(uint32_t*)&v;
        }
        if (okhi) {
            __half2 v = __floats2half2_rn(acc[t][2] + b0, acc[t][3] + b1);
            yh[nhi * 32 + (c >> 1)] = *(uint32_t*)&v;
        }
    }
}

// ---------------------------------------------------------------------------
// K1: node message MLP  y = relu(x @ W1 + b1) @ W2 + b2   -> fp16 g_yh
// Zeroes this block's g_agg slice; block 0 detects edge_index dtype.
// Smem 51.2KB -> 4 CTAs/SM (W2 re-staged into the W1 buffer between layers).
// ---------------------------------------------------------------------------
#define K1_SMEM_FLOATS (TROWS * PITCH + 4096)

__global__ __launch_bounds__(256) void k_msg_mlp(
    const float* __restrict__ x,
    const float* __restrict__ w1, const float* __restrict__ b1,
    const float* __restrict__ w2, const float* __restrict__ b2,
    const int* __restrict__ ei32)
{
    extern __shared__ float sm[];
    float* xs = sm;                    // 128*68 tile (x, then h)
    float* wt = xs + TROWS * PITCH;    // 4096 (W1, then W2)

    const int tid = threadIdx.x;
    const int n0  = blockIdx.x * TROWS;
    const int lane = tid & 31, warp = tid >> 5;
    const int g = lane >> 2, tig = lane & 3;
    const int r0 = warp * 16;

    // Zero this block's g_agg slice (scatter runs after this kernel).
    {
        float4 z = make_float4(0.f, 0.f, 0.f, 0.f);
#pragma unroll
        for (int it = 0; it < 8; it++) {
            int i = n0 * 16 + tid + it * 256;
            if (i < N_NODES * 16) g_agg4[i] = z;
        }
    }
    if (blockIdx.x == 0 && tid == 0) {
        int is64 = 1;
        for (int i = 0; i < 64; i++)
            if (ei32[2 * i + 1] != 0) { is64 = 0; break; }
        g_ei_is64 = is64;
    }

    stage_w(wt, w1, 64, tid);
    stage_tile(xs, (const float4*)(x + (size_t)n0 * D), n0, tid);
    __syncthreads();

    float acc[8][4];
    zero_acc(acc);
    mma_sweep(acc, xs, wt, r0, g, tig);    // reads only warp-own tile rows
    __syncwarp();
    write_h(xs, acc, b1, r0, g, tig);      // writes only warp-own tile rows
    __syncthreads();                        // all W1 reads done
    stage_w(wt, w2, 64, tid);               // W2 over W1
    __syncthreads();

    zero_acc(acc);
    mma_sweep(acc, xs, wt, r0, g, tig);
    store_out_h(acc, b2, n0, r0, g, tig);
}

// ---------------------------------------------------------------------------
// K2: scatter  agg[col] += y[row]  (fp16 read, f32 vector reduction)
// 16 threads/edge; thread c covers cols 4c..4c+3 (uint2 = 4 halves).
// ---------------------------------------------------------------------------
__global__ __launch_bounds__(256) void k_scatter(const void* __restrict__ ei_raw)
{
    long long tid = (long long)blockIdx.x * blockDim.x + threadIdx.x;
    if (tid >= (long long)N_EDGES * 16) return;
    int e = (int)(tid >> 4);
    int c = (int)(tid & 15);

    int row, col;
    if (g_ei_is64) {
        const long long* ei = (const long long*)ei_raw;
        row = (int)ei[e];
        col = (int)ei[N_EDGES + e];
    } else {
        const int* ei = (const int*)ei_raw;
        row = ei[e];
        col = ei[N_EDGES + e];
    }
    if ((unsigned)row >= N_NODES || (unsigned)col >= N_NODES) return;

    uint2 p = g_yh[(size_t)row * 16 + c];
    float2 lo = __half22float2(*(__half2*)&p.x);
    float2 hi = __half22float2(*(__half2*)&p.y);
    float4* q = g_agg4 + (size_t)col * (D / 4) + c;
    asm volatile("red.global.add.v4.f32 [%0], {%1,%2,%3,%4};"
                 :: "l"(q), "f"(lo.x), "f"(lo.y), "f"(hi.x), "f"(hi.y)
                 : "memory");
}

// ---------------------------------------------------------------------------
// K3: output MLP  out = relu([x,agg] @ W1 + b1) @ W2 + b2     [N,64]
// Two-pass layer 1 (x vs W1[0:64], agg vs W1[64:128]); W2 re-staged into the
// W1 buffer for layer 2. Smem 67.6KB -> 3 CTAs/SM.
// ---------------------------------------------------------------------------
#define K3_SMEM_FLOATS (TROWS * PITCH + 8192)

__global__ __launch_bounds__(256) void k_out_mlp(
    const float* __restrict__ x,
    const float* __restrict__ w1, const float* __restrict__ b1,
    const float* __restrict__ w2, const float* __restrict__ b2,
    float* __restrict__ out)
{
    extern __shared__ float sm[];
    float* xs = sm;                    // 128*68 tile (x, agg, then h)
    float* wt = xs + TROWS * PITCH;    // 8192 (W1 128 k-rows, then W2 in first half)

    const int tid = threadIdx.x;
    const int n0  = blockIdx.x * TROWS;
    const int lane = tid & 31, warp = tid >> 5;
    const int g = lane >> 2, tig = lane & 3;
    const int r0 = warp * 16;

    stage_w(wt, w1, 128, tid);
    stage_tile(xs, (const float4*)(x + (size_t)n0 * D), n0, tid);
    __syncthreads();

    float acc[8][4];
    zero_acc(acc);
    mma_sweep(acc, xs, wt, r0, g, tig);             // k = 0..63 (x)
    __syncthreads();                                 // all x-tile reads done

    stage_tile(xs, (const float4*)(g_agg4 + (size_t)n0 * (D / 4)), n0, tid);
    __syncthreads();
    mma_sweep(acc, xs, wt + 64 * 64, r0, g, tig);   // k = 64..127 (agg)
    __syncwarp();
    write_h(xs, acc, b1, r0, g, tig);
    __syncthreads();                                 // all W1 + agg reads done
    stage_w(wt, w2, 64, tid);                        // W2 over W1
    __syncthreads();

    zero_acc(acc);
    mma_sweep(acc, xs, wt, r0, g, tig);
    store_out(out, acc, b2, n0, r0, g, tig);
}

// ---------------------------------------------------------------------------
// Launch. Inputs: 0 x, 1 edge_index, 2 batch, 3..6 msg mlp, 7..10 out mlp
// ---------------------------------------------------------------------------
extern "C" void kernel_launch(void* const* d_in, const int* in_sizes, int n_in,
                              void* d_out, int out_size)
{
    const float* x      = (const float*)d_in[0];
    const void*  ei     = d_in[1];
    const float* msg_w1 = (const float*)d_in[3];
    const float* msg_b1 = (const float*)d_in[4];
    const float* msg_w2 = (const float*)d_in[5];
    const float* msg_b2 = (const float*)d_in[6];
    const float* out_w1 = (const float*)d_in[7];
    const float* out_b1 = (const float*)d_in[8];
    const float* out_w2 = (const float*)d_in[9];
    const float* out_b2 = (const float*)d_in[10];
    float*       out    = (float*)d_out;

    const int smem1 = K1_SMEM_FLOATS * sizeof(float);   // ~51.2 KB
    const int smem3 = K3_SMEM_FLOATS * sizeof(float);   // ~67.6 KB
    cudaFuncSetAttribute(k_msg_mlp, cudaFuncAttributeMaxDynamicSharedMemorySize, smem1);
    cudaFuncSetAttribute(k_out_mlp, cudaFuncAttributeMaxDynamicSharedMemorySize, smem3);

    const int nodeBlocks = (N_NODES + TROWS - 1) / TROWS;   // 782

    k_msg_mlp<<<nodeBlocks, 256, smem1>>>(x, msg_w1, msg_b1, msg_w2, msg_b2,
                                          (const int*)ei);
    {
        long long work = (long long)N_EDGES * 16;
        int blocks = (int)((work + 255) / 256);
        k_scatter<<<blocks, 256>>>(ei);
    }
    k_out_mlp<<<nodeBlocks, 256, smem3>>>(x, out_w1, out_b1, out_w2, out_b2, out);
}

// round 11
// speedup vs baseline: 2.4464x; 1.4290x over previous
#include <cuda_runtime.h>
#include <cuda_fp16.h>
#include <cstdint>

#define N_NODES 100000
#define N_EDGES 1000000
#define D 64

// Scratch: device globals (no allocs allowed).
__device__ uint4 g_yh[(size_t)N_NODES * 8];    // message MLP output, fp16 (64 halves/row)
__device__ uint4 g_aggh[(size_t)N_NODES * 8];  // scatter-sum accumulator, fp16
__device__ int   g_ei_is64;                    // 1 if edge_index is int64

// fp32 -> tf32 (round-to-nearest-away), kept in a 32-bit float slot.
__device__ __forceinline__ uint32_t f2tf(float f) {
    uint32_t r; asm("cvt.rna.tf32.f32 %0, %1;" : "=r"(r) : "f"(f)); return r;
}
__device__ __forceinline__ float f2tff(float f) { return __uint_as_float(f2tf(f)); }

// ---------------------------------------------------------------------------
// Tensor-core MLP building blocks.
// CTA = 256 threads (8 warps); tile = 128 rows x 64 cols, pitch 68 floats.
// Warp w owns rows [16w, 16w+16) x all 64 cols: 8 mma tiles of m16n8k8.
// Weights in smem row-major [k][c] with col swizzle c ^ 8*(k&3).
// ---------------------------------------------------------------------------
#define PITCH 68
#define TROWS 128

// Stage 128x64 f32 gmem slab into pitch-68 tile, tf32-rounded, zero-padded.
__device__ __forceinline__ void stage_tile(float* xs, const float4* src4,
                                           int n0, int tid) {
#pragma unroll
    for (int it = 0; it < 8; it++) {
        int i = tid + it * 256;                 // float4 index, 2048 total
        int l = i >> 4, kq = i & 15;
        float4 v = make_float4(0.f, 0.f, 0.f, 0.f);
        if (n0 + l < N_NODES) v = src4[i];
        v.x = f2tff(v.x); v.y = f2tff(v.y); v.z = f2tff(v.z); v.w = f2tff(v.w);
        *(float4*)(xs + l * PITCH + 4 * kq) = v;
    }
}

// Stage 128x64 fp16 slab (8 x uint4 per row) into the tile. fp16 mantissa
// (10 bits) fits tf32 exactly -> no extra rounding step needed.
__device__ __forceinline__ void stage_tile_h(float* xs, const uint4* src,
                                             int n0, int tid) {
#pragma unroll
    for (int it = 0; it < 4; it++) {
        int i = tid + it * 256;                 // uint4 index, 1024 total
        int l = i >> 3, kq = i & 7;
        uint4 v = make_uint4(0u, 0u, 0u, 0u);
        if (n0 + l < N_NODES) v = src[i];
        float* p = xs + l * PITCH + 8 * kq;
        float2 f0 = __half22float2(*(__half2*)&v.x);
        float2 f1 = __half22float2(*(__half2*)&v.y);
        float2 f2 = __half22float2(*(__half2*)&v.z);
        float2 f3 = __half22float2(*(__half2*)&v.w);
        *(float4*)(p)     = make_float4(f0.x, f0.y, f1.x, f1.y);
        *(float4*)(p + 4) = make_float4(f2.x, f2.y, f3.x, f3.y);
    }
}

// Stage Krows x 64 weights (float4 path), tf32-rounded, XOR bank swizzle.
__device__ __forceinline__ void stage_w(float* ws, const float* __restrict__ w,
                                        int Krows, int tid) {
    const float4* w4 = (const float4*)w;
    for (int i = tid; i < Krows * 16; i += 256) {
        int k = i >> 4, c0 = (i & 15) * 4;
        float4 v = w4[i];
        v.x = f2tff(v.x); v.y = f2tff(v.y); v.z = f2tff(v.z); v.w = f2tff(v.w);
        *(float4*)(ws + k * 64 + (c0 ^ (8 * (k & 3)))) = v;
    }
}

// acc += tile[r0..r0+15][0..64) @ W[0..64)[0..64)
__device__ __forceinline__ void mma_sweep(float acc[8][4], const float* xs,
                                          const float* ws, int r0, int g, int tig) {
#pragma unroll
    for (int s = 0; s < 8; s++) {
        const int k0 = 8 * s;
        const float* xr0 = xs + (r0 + g) * PITCH + k0 + tig;
        const float* xr8 = xs + (r0 + 8 + g) * PITCH + k0 + tig;
        uint32_t a0 = __float_as_uint(xr0[0]);
        uint32_t a1 = __float_as_uint(xr8[0]);
        uint32_t a2 = __float_as_uint(xr0[4]);
        uint32_t a3 = __float_as_uint(xr8[4]);
        const float* w0 = ws + (k0 + tig) * 64;
        const float* w4 = ws + (k0 + 4 + tig) * 64;
        const int xm = 8 * tig;
#pragma unroll
        for (int t = 0; t < 8; t++) {
            int c = (8 * t + g) ^ xm;
            uint32_t b0 = __float_as_uint(w0[c]);
            uint32_t b1 = __float_as_uint(w4[c]);
            asm volatile(
                "mma.sync.aligned.m16n8k8.row.col.f32.tf32.tf32.f32 "
                "{%0,%1,%2,%3}, {%4,%5,%6,%7}, {%8,%9}, {%0,%1,%2,%3};"
                : "+f"(acc[t][0]), "+f"(acc[t][1]), "+f"(acc[t][2]), "+f"(acc[t][3])
                : "r"(a0), "r"(a1), "r"(a2), "r"(a3), "r"(b0), "r"(b1));
        }
    }
}

__device__ __forceinline__ void zero_acc(float acc[8][4]) {
#pragma unroll
    for (int t = 0; t < 8; t++)
#pragma unroll
        for (int p = 0; p < 4; p++) acc[t][p] = 0.f;
}

// relu(acc+bias), tf32-round, write back into the tile (warp-own rows).
__device__ __forceinline__ void write_h(float* xs, float acc[8][4],
                                        const float* __restrict__ bias,
                                        int r0, int g, int tig) {
#pragma unroll
    for (int t = 0; t < 8; t++) {
        int c = 8 * t + 2 * tig;
        float b0 = __ldg(bias + c), b1 = __ldg(bias + c + 1);
        float2 lo, hi;
        lo.x = f2tff(fmaxf(acc[t][0] + b0, 0.f));
        lo.y = f2tff(fmaxf(acc[t][1] + b1, 0.f));
        hi.x = f2tff(fmaxf(acc[t][2] + b0, 0.f));
        hi.y = f2tff(fmaxf(acc[t][3] + b1, 0.f));
        *(float2*)(xs + (r0 + g) * PITCH + c)     = lo;
        *(float2*)(xs + (r0 + 8 + g) * PITCH + c) = hi;
    }
}

// acc+bias -> f32 gmem (guarded), float2 per mma tile-row.
__device__ __forceinline__ void store_out(float* dst, float acc[8][4],
                                          const float* __restrict__ bias,
                                          int n0, int r0, int g, int tig) {
    int nlo = n0 + r0 + g, nhi = nlo + 8;
    bool oklo = nlo < N_NODES, okhi = nhi < N_NODES;
#pragma unroll
    for (int t = 0; t < 8; t++) {
        int c = 8 * t + 2 * tig;
        float b0 = __ldg(bias + c), b1 = __ldg(bias + c + 1);
        if (oklo) {
            float2 v; v.x = acc[t][0] + b0; v.y = acc[t][1] + b1;
            *(float2*)(dst + (size_t)nlo * D + c) = v;
        }
        if (okhi) {
            float2 v; v.x = acc[t][2] + b0; v.y = acc[t][3] + b1;
            *(float2*)(dst + (size_t)nhi * D + c) = v;
        }
    }
}

// acc+bias -> fp16 y buffer (guarded), one half2 (4B) per mma tile-row.
__device__ __forceinline__ void store_out_h(float acc[8][4],
                                            const float* __restrict__ bias,
                                            int n0, int r0, int g, int tig) {
    uint32_t* yh = (uint32_t*)g_yh;   // 32 uints per row
    int nlo = n0 + r0 + g, nhi = nlo + 8;
    bool oklo = nlo < N_NODES, okhi = nhi < N_NODES;
#pragma unroll
    for (int t = 0; t < 8; t++) {
        int c = 8 * t + 2 * tig;
        float b0 = __ldg(bias + c), b1 = __ldg(bias + c + 1);
        if (oklo) {
            __half2 v = __floats2half2_rn(acc[t][0] + b0, acc[t][1] + b1);
            yh[nlo * 32 + (c >> 1)] = *(uint32_t*)&v;
        }
        if (okhi) {
            __half2 v = __floats2half2_rn(acc[t][2] + b0, acc[t][3] + b1);
            yh[nhi * 32 + (c >> 1)] = *(uint32_t*)&v;
        }
    }
}

// ---------------------------------------------------------------------------
// K1: node message MLP  y = relu(x @ W1 + b1) @ W2 + b2   -> fp16 g_yh
// Zeroes this block's g_aggh slice; block 0 detects edge_index dtype.
// Smem ~50.8KB -> 4 CTAs/SM.
// ---------------------------------------------------------------------------
#define K1_SMEM_FLOATS (TROWS * PITCH + 4096)

__global__ __launch_bounds__(256) void k_msg_mlp(
    const float* __restrict__ x,
    const float* __restrict__ w1, const float* __restrict__ b1,
    const float* __restrict__ w2, const float* __restrict__ b2,
    const int* __restrict__ ei32)
{
    extern __shared__ float sm[];
    float* xs = sm;                    // 128*68 tile (x, then h)
    float* wt = xs + TROWS * PITCH;    // 4096 (W1, then W2)

    const int tid = threadIdx.x;
    const int n0  = blockIdx.x * TROWS;
    const int lane = tid & 31, warp = tid >> 5;
    const int g = lane >> 2, tig = lane & 3;
    const int r0 = warp * 16;

    // Zero this block's g_aggh slice (fp16: 8 x uint4 per row).
    {
        uint4 z = make_uint4(0u, 0u, 0u, 0u);
#pragma unroll
        for (int it = 0; it < 4; it++) {
            int i = n0 * 8 + tid + it * 256;
            if (i < N_NODES * 8) g_aggh[i] = z;
        }
    }
    if (blockIdx.x == 0 && tid == 0) {
        int is64 = 1;
        for (int i = 0; i < 64; i++)
            if (ei32[2 * i + 1] != 0) { is64 = 0; break; }
        g_ei_is64 = is64;
    }

    stage_w(wt, w1, 64, tid);
    stage_tile(xs, (const float4*)(x + (size_t)n0 * D), n0, tid);
    __syncthreads();

    float acc[8][4];
    zero_acc(acc);
    mma_sweep(acc, xs, wt, r0, g, tig);    // reads only warp-own tile rows
    __syncwarp();
    write_h(xs, acc, b1, r0, g, tig);      // writes only warp-own tile rows
    __syncthreads();                        // all W1 reads done
    stage_w(wt, w2, 64, tid);               // W2 over W1
    __syncthreads();

    zero_acc(acc);
    mma_sweep(acc, xs, wt, r0, g, tig);
    store_out_h(acc, b2, n0, r0, g, tig);
}

// ---------------------------------------------------------------------------
// K2: scatter  agg[col] += y[row]  -- all fp16: 8 threads/edge, each does one
// 16B load + one red.global.add.noftz.v4.f16x2 (8 halves per RED).
// ---------------------------------------------------------------------------
__global__ __launch_bounds__(256) void k_scatter(const void* __restrict__ ei_raw)
{
    int tid = blockIdx.x * blockDim.x + threadIdx.x;
    if (tid >= N_EDGES * 8) return;
    int e = tid >> 3;
    int c = tid & 7;

    int row, col;
    if (g_ei_is64) {
        const long long* ei = (const long long*)ei_raw;
        row = (int)ei[e];
        col = (int)ei[N_EDGES + e];
    } else {
        const int* ei = (const int*)ei_raw;
        row = ei[e];
        col = ei[N_EDGES + e];
    }
    if ((unsigned)row >= N_NODES || (unsigned)col >= N_NODES) return;

    uint4 v = g_yh[(size_t)row * 8 + c];
    uint4* q = g_aggh + (size_t)col * 8 + c;
    asm volatile("red.global.add.noftz.v4.f16x2 [%0], {%1,%2,%3,%4};"
                 :: "l"(q), "r"(v.x), "r"(v.y), "r"(v.z), "r"(v.w)
                 : "memory");
}

// ---------------------------------------------------------------------------
// K3: output MLP  out = relu([x,agg] @ W1 + b1) @ W2 + b2     [N,64]
// Three weight stages through ONE 16KB buffer: W1[0:64] (x pass),
// W1[64:128] (agg pass), W2 (layer 2). Smem ~50.8KB -> 4 CTAs/SM.
// ---------------------------------------------------------------------------
#define K3_SMEM_FLOATS (TROWS * PITCH + 4096)

__global__ __launch_bounds__(256) void k_out_mlp(
    const float* __restrict__ x,
    const float* __restrict__ w1, const float* __restrict__ b1,
    const float* __restrict__ w2, const float* __restrict__ b2,
    float* __restrict__ out)
{
    extern __shared__ float sm[];
    float* xs = sm;                    // 128*68 tile (x, agg, then h)
    float* wt = xs + TROWS * PITCH;    // 4096 (W1a, W1b, then W2)

    const int tid = threadIdx.x;
    const int n0  = blockIdx.x * TROWS;
    const int lane = tid & 31, warp = tid >> 5;
    const int g = lane >> 2, tig = lane & 3;
    const int r0 = warp * 16;

    stage_w(wt, w1, 64, tid);                        // W1 rows 0..63
    stage_tile(xs, (const float4*)(x + (size_t)n0 * D), n0, tid);
    __syncthreads();

    float acc[8][4];
    zero_acc(acc);
    mma_sweep(acc, xs, wt, r0, g, tig);              // k = 0..63 (x)
    __syncthreads();                                  // x tile + W1a reads done

    stage_tile_h(xs, g_aggh + (size_t)n0 * 8, n0, tid);
    stage_w(wt, w1 + 64 * 64, 64, tid);              // W1 rows 64..127
    __syncthreads();
    mma_sweep(acc, xs, wt, r0, g, tig);              // k = 64..127 (agg)
    __syncwarp();
    write_h(xs, acc, b1, r0, g, tig);
    __syncthreads();                                  // agg tile + W1b reads done
    stage_w(wt, w2, 64, tid);                        // W2
    __syncthreads();

    zero_acc(acc);
    mma_sweep(acc, xs, wt, r0, g, tig);
    store_out(out, acc, b2, n0, r0, g, tig);
}

// ---------------------------------------------------------------------------
// Launch. Inputs: 0 x, 1 edge_index, 2 batch, 3..6 msg mlp, 7..10 out mlp
// ---------------------------------------------------------------------------
extern "C" void kernel_launch(void* const* d_in, const int* in_sizes, int n_in,
                              void* d_out, int out_size)
{
    const float* x      = (const float*)d_in[0];
    const void*  ei     = d_in[1];
    const float* msg_w1 = (const float*)d_in[3];
    const float* msg_b1 = (const float*)d_in[4];
    const float* msg_w2 = (const float*)d_in[5];
    const float* msg_b2 = (const float*)d_in[6];
    const float* out_w1 = (const float*)d_in[7];
    const float* out_b1 = (const float*)d_in[8];
    const float* out_w2 = (const float*)d_in[9];
    const float* out_b2 = (const float*)d_in[10];
    float*       out    = (float*)d_out;

    const int smem1 = K1_SMEM_FLOATS * sizeof(float);   // ~50.8 KB
    const int smem3 = K3_SMEM_FLOATS * sizeof(float);   // ~50.8 KB
    cudaFuncSetAttribute(k_msg_mlp, cudaFuncAttributeMaxDynamicSharedMemorySize, smem1);
    cudaFuncSetAttribute(k_out_mlp, cudaFuncAttributeMaxDynamicSharedMemorySize, smem3);

    const int nodeBlocks = (N_NODES + TROWS - 1) / TROWS;   // 782

    k_msg_mlp<<<nodeBlocks, 256, smem1>>>(x, msg_w1, msg_b1, msg_w2, msg_b2,
                                          (const int*)ei);
    k_scatter<<<(N_EDGES * 8 + 255) / 256, 256>>>(ei);
    k_out_mlp<<<nodeBlocks, 256, smem3>>>(x, out_w1, out_b1, out_w2, out_b2, out);
}